// round 3
// baseline (speedup 1.0000x reference)
#include <cuda_runtime.h>
#include <math.h>

#define B_  8
#define T_  1024
#define D_  1024
#define H_  16
#define G_  4
#define HD_ 64
#define KVD_ (G_*HD_)   // 256
#define NREL 255        // 2*128-1

// -------- scratch (static device arrays; no runtime allocation) --------
__device__ float g_q[(size_t)B_*T_*D_];     // scaled q, [B*T, D] head-interleaved
__device__ float g_k[(size_t)B_*T_*KVD_];   // [B*T, 256]
__device__ float g_v[(size_t)B_*T_*KVD_];
__device__ float g_o[(size_t)B_*T_*D_];     // attention out, [B*T, D]

// ============================================================
// fp32 GEMM: C[M,N] = alpha * A[M,K] @ B[N,K]^T
// 128x64 block, BK=16, 256 threads, 8x4 register tile.
// Requires M%128==0, N%64==0, K%16==0.
// ============================================================
__global__ __launch_bounds__(256) void gemm_nt(
    const float* __restrict__ A, const float* __restrict__ Bm,
    float* __restrict__ C, int M, int N, int K, float alpha)
{
    __shared__ float As[16][132];   // [k][m]
    __shared__ float Bs[16][68];    // [k][n]
    const int tid = threadIdx.x;
    const int tx = tid & 15;        // n: 4 cols each -> 64
    const int ty = tid >> 4;        // m: 8 rows each -> 128
    const int m0 = blockIdx.y * 128, n0 = blockIdx.x * 64;

    // A-load mapping: 512 float4s, 2 per thread
    const int arow0 = tid >> 2;             // 0..63
    const int ak    = (tid & 3) << 2;       // 0,4,8,12
    const float* Ap0 = A + (size_t)(m0 + arow0)      * K + ak;
    const float* Ap1 = A + (size_t)(m0 + arow0 + 64) * K + ak;
    // B-load mapping: 256 float4s, 1 per thread
    const int brow = tid >> 2;              // 0..63
    const int bk   = (tid & 3) << 2;
    const float* Bp = Bm + (size_t)(n0 + brow) * K + bk;

    float acc[8][4];
#pragma unroll
    for (int i = 0; i < 8; i++)
#pragma unroll
        for (int j = 0; j < 4; j++) acc[i][j] = 0.f;

    for (int k0 = 0; k0 < K; k0 += 16) {
        float4 a0 = *(const float4*)(Ap0 + k0);
        float4 a1 = *(const float4*)(Ap1 + k0);
        float4 bv = *(const float4*)(Bp + k0);
        As[ak+0][arow0] = a0.x; As[ak+1][arow0] = a0.y;
        As[ak+2][arow0] = a0.z; As[ak+3][arow0] = a0.w;
        As[ak+0][arow0+64] = a1.x; As[ak+1][arow0+64] = a1.y;
        As[ak+2][arow0+64] = a1.z; As[ak+3][arow0+64] = a1.w;
        Bs[bk+0][brow] = bv.x; Bs[bk+1][brow] = bv.y;
        Bs[bk+2][brow] = bv.z; Bs[bk+3][brow] = bv.w;
        __syncthreads();
#pragma unroll
        for (int kk = 0; kk < 16; kk++) {
            float4 am0 = *(const float4*)&As[kk][(ty << 3) + 0];
            float4 am1 = *(const float4*)&As[kk][(ty << 3) + 4];
            float4 bn  = *(const float4*)&Bs[kk][tx << 2];
            float ar[8] = {am0.x, am0.y, am0.z, am0.w, am1.x, am1.y, am1.z, am1.w};
            float br[4] = {bn.x, bn.y, bn.z, bn.w};
#pragma unroll
            for (int i = 0; i < 8; i++)
#pragma unroll
                for (int j = 0; j < 4; j++)
                    acc[i][j] += ar[i] * br[j];
        }
        __syncthreads();
    }
#pragma unroll
    for (int i = 0; i < 8; i++) {
        float4 o4;
        o4.x = alpha * acc[i][0]; o4.y = alpha * acc[i][1];
        o4.z = alpha * acc[i][2]; o4.w = alpha * acc[i][3];
        *(float4*)&C[(size_t)(m0 + (ty << 3) + i) * N + n0 + (tx << 2)] = o4;
    }
}

// ============================================================
// Fused flash attention + relative-position bias.
// Grid: (T/64, H, B), 256 threads.
// q is pre-scaled by 1/sqrt(hd). bias[q,k] = qe[q][clamp(q-k,-127,127)+127]
// where qe = q_tile @ E^T (computed in prologue).
// ============================================================
#define QS(d,qq) qsT[(d)*68 + (qq)]
#define KS(d,cc) ksT[(d)*68 + (cc)]
#define VS(cc,d) vsm[(cc)*68 + (d)]
#define PS(rr,cc) psm[(rr)*68 + (cc)]
#define QE(rr,p) qem[(rr)*256 + (p)]

#define ATTN_SMEM_BYTES ((4*64*68 + 64*256) * 4)

__global__ __launch_bounds__(256) void attn_kernel(
    const float* __restrict__ q, const float* __restrict__ k,
    const float* __restrict__ v, const float* __restrict__ E,
    float* __restrict__ o)
{
    extern __shared__ float sm[];
    float* qsT = sm;              // [64 d][68 q]
    float* ksT = qsT + 64*68;     // [64 d][68 k]   (also E tile in prologue)
    float* vsm = ksT + 64*68;     // [64 k][68 d]
    float* psm = vsm + 64*68;     // [64 q][68 k]
    float* qem = psm + 64*68;     // [64 q][256 p]

    const int tid = threadIdx.x;
    const int tx = tid & 15, ty = tid >> 4;
    const int r0  = ty << 2;      // q rows owned by this thread
    const int c0  = tx << 2;      // cols (k / d) owned by this thread
    const int q0 = blockIdx.x * 64;
    const int h  = blockIdx.y;
    const int b  = blockIdx.z;
    const int g  = h >> 2;        // kv group = h / (H/G)

    // ---- load q tile (transposed into smem) ----
    const float* qbase = q + ((size_t)(b * T_ + q0)) * D_ + h * HD_;
    for (int idx = tid; idx < 64 * 64; idx += 256) {
        int r = idx >> 6, d = idx & 63;
        QS(d, r) = qbase[(size_t)r * D_ + d];
    }
    __syncthreads();

    // ---- prologue: qe[r][p] = sum_d q[r][d] * E[p][d], p in [0,255) ----
    for (int p0 = 0; p0 < NREL; p0 += 64) {
        int np = NREL - p0; if (np > 64) np = 64;
        for (int idx = tid; idx < np * 64; idx += 256) {
            int p = idx >> 6, d = idx & 63;
            KS(d, p) = E[(size_t)(p0 + p) * HD_ + d];
        }
        __syncthreads();
        float aq[4][4];
#pragma unroll
        for (int i = 0; i < 4; i++)
#pragma unroll
            for (int j = 0; j < 4; j++) aq[i][j] = 0.f;
#pragma unroll 8
        for (int d = 0; d < 64; d++) {
            float4 a4 = *(const float4*)&QS(d, r0);
            float4 e4 = *(const float4*)&KS(d, c0);
            float ar[4] = {a4.x, a4.y, a4.z, a4.w};
            float er[4] = {e4.x, e4.y, e4.z, e4.w};
#pragma unroll
            for (int i = 0; i < 4; i++)
#pragma unroll
                for (int j = 0; j < 4; j++)
                    aq[i][j] += ar[i] * er[j];
        }
#pragma unroll
        for (int i = 0; i < 4; i++)
#pragma unroll
            for (int j = 0; j < 4; j++)
                if (c0 + j < np) QE(r0 + i, p0 + c0 + j) = aq[i][j];
        __syncthreads();
    }

    // ---- online-softmax state ----
    float m_r[4], l_r[4], acc[4][4];
#pragma unroll
    for (int i = 0; i < 4; i++) { m_r[i] = -1e30f; l_r[i] = 0.f; }
#pragma unroll
    for (int i = 0; i < 4; i++)
#pragma unroll
        for (int j = 0; j < 4; j++) acc[i][j] = 0.f;

    const float* kbase = k + (size_t)b * T_ * KVD_ + g * HD_;
    const float* vbase = v + (size_t)b * T_ * KVD_ + g * HD_;

    // ---- main loop over key tiles ----
    for (int kt = 0; kt < T_; kt += 64) {
        for (int idx = tid; idx < 64 * 64; idx += 256) {
            int c = idx >> 6, d = idx & 63;
            KS(d, c) = kbase[(size_t)(kt + c) * KVD_ + d];
            VS(c, d) = vbase[(size_t)(kt + c) * KVD_ + d];
        }
        __syncthreads();

        // scores s = q @ k^T
        float s[4][4];
#pragma unroll
        for (int i = 0; i < 4; i++)
#pragma unroll
            for (int j = 0; j < 4; j++) s[i][j] = 0.f;
#pragma unroll 8
        for (int kk = 0; kk < 64; kk++) {
            float4 a4 = *(const float4*)&QS(kk, r0);
            float4 b4 = *(const float4*)&KS(kk, c0);
            float ar[4] = {a4.x, a4.y, a4.z, a4.w};
            float br[4] = {b4.x, b4.y, b4.z, b4.w};
#pragma unroll
            for (int i = 0; i < 4; i++)
#pragma unroll
                for (int j = 0; j < 4; j++)
                    s[i][j] += ar[i] * br[j];
        }

        // + relative position bias (dist = q - k, clamped)
#pragma unroll
        for (int i = 0; i < 4; i++) {
            int qg = q0 + r0 + i;
#pragma unroll
            for (int j = 0; j < 4; j++) {
                int dlt = qg - (kt + c0 + j);
                dlt = max(-127, min(127, dlt));
                s[i][j] += QE(r0 + i, dlt + 127);
            }
        }

        // online softmax update (row stats over 16-lane groups)
#pragma unroll
        for (int i = 0; i < 4; i++) {
            float tm = fmaxf(fmaxf(s[i][0], s[i][1]), fmaxf(s[i][2], s[i][3]));
            tm = fmaxf(tm, __shfl_xor_sync(0xffffffffu, tm, 1));
            tm = fmaxf(tm, __shfl_xor_sync(0xffffffffu, tm, 2));
            tm = fmaxf(tm, __shfl_xor_sync(0xffffffffu, tm, 4));
            tm = fmaxf(tm, __shfl_xor_sync(0xffffffffu, tm, 8));
            float mnew = fmaxf(m_r[i], tm);
            float scl = __expf(m_r[i] - mnew);
            float ls = 0.f;
#pragma unroll
            for (int j = 0; j < 4; j++) {
                s[i][j] = __expf(s[i][j] - mnew);
                ls += s[i][j];
            }
            ls += __shfl_xor_sync(0xffffffffu, ls, 1);
            ls += __shfl_xor_sync(0xffffffffu, ls, 2);
            ls += __shfl_xor_sync(0xffffffffu, ls, 4);
            ls += __shfl_xor_sync(0xffffffffu, ls, 8);
            l_r[i] = l_r[i] * scl + ls;
            m_r[i] = mnew;
#pragma unroll
            for (int j = 0; j < 4; j++) acc[i][j] *= scl;
            *(float4*)&PS(r0 + i, c0) = make_float4(s[i][0], s[i][1], s[i][2], s[i][3]);
        }
        __syncthreads();

        // acc += p @ v
#pragma unroll 4
        for (int kk = 0; kk < 64; kk++) {
            float pa[4];
#pragma unroll
            for (int i = 0; i < 4; i++) pa[i] = PS(r0 + i, kk);
            float4 v4 = *(const float4*)&VS(kk, c0);
            float vr[4] = {v4.x, v4.y, v4.z, v4.w};
#pragma unroll
            for (int i = 0; i < 4; i++)
#pragma unroll
                for (int j = 0; j < 4; j++)
                    acc[i][j] += pa[i] * vr[j];
        }
        __syncthreads();
    }

    // ---- epilogue ----
    float* obase = o + ((size_t)(b * T_ + q0)) * D_ + h * HD_;
#pragma unroll
    for (int i = 0; i < 4; i++) {
        float inv = 1.0f / l_r[i];
        float4 o4 = make_float4(acc[i][0] * inv, acc[i][1] * inv,
                                acc[i][2] * inv, acc[i][3] * inv);
        *(float4*)&obase[(size_t)(r0 + i) * D_ + c0] = o4;
    }
}

// ============================================================
extern "C" void kernel_launch(void* const* d_in, const int* in_sizes, int n_in,
                              void* d_out, int out_size)
{
    const float* x  = (const float*)d_in[0];
    const float* Wq = (const float*)d_in[1];
    const float* Wk = (const float*)d_in[2];
    const float* Wv = (const float*)d_in[3];
    const float* Wo = (const float*)d_in[4];
    const float* E  = (const float*)d_in[5];
    float* out = (float*)d_out;

    float *qp, *kp, *vp, *op;
    cudaGetSymbolAddress((void**)&qp, g_q);
    cudaGetSymbolAddress((void**)&kp, g_k);
    cudaGetSymbolAddress((void**)&vp, g_v);
    cudaGetSymbolAddress((void**)&op, g_o);

    cudaFuncSetAttribute(attn_kernel,
                         cudaFuncAttributeMaxDynamicSharedMemorySize,
                         ATTN_SMEM_BYTES);

    const int M = B_ * T_;               // 8192
    const float qscale = 0.125f;         // 1/sqrt(64)

    // q = (x @ Wq^T) * qscale
    gemm_nt<<<dim3(D_ / 64, M / 128), 256>>>(x, Wq, qp, M, D_, D_, qscale);
    // k = x @ Wk^T ; v = x @ Wv^T
    gemm_nt<<<dim3(KVD_ / 64, M / 128), 256>>>(x, Wk, kp, M, KVD_, D_, 1.0f);
    gemm_nt<<<dim3(KVD_ / 64, M / 128), 256>>>(x, Wv, vp, M, KVD_, D_, 1.0f);
    // fused attention with relpos bias
    attn_kernel<<<dim3(T_ / 64, H_, B_), 256, ATTN_SMEM_BYTES>>>(qp, kp, vp, E, op);
    // out = o @ Wo^T
    gemm_nt<<<dim3(D_ / 64, M / 128), 256>>>(op, Wo, out, M, D_, D_, 1.0f);
}

// round 11
// speedup vs baseline: 1.2050x; 1.2050x over previous
#include <cuda_runtime.h>
#include <cuda_bf16.h>
#include <math.h>

#define B_  8
#define T_  1024
#define D_  1024
#define H_  16
#define G_  4
#define HD_ 64
#define KVD_ 256
#define NREL 255

// ================= scratch (static device arrays) =================
__device__ float g_q[(size_t)B_*T_*D_];
__device__ float g_k[(size_t)B_*T_*KVD_];
__device__ float g_v[(size_t)B_*T_*KVD_];
__device__ float g_o[(size_t)B_*T_*D_];

__device__ __align__(16) __nv_bfloat16 g_xh[(size_t)B_*T_*D_];
__device__ __align__(16) __nv_bfloat16 g_xl[(size_t)B_*T_*D_];
__device__ __align__(16) __nv_bfloat16 g_oh[(size_t)B_*T_*D_];
__device__ __align__(16) __nv_bfloat16 g_ol[(size_t)B_*T_*D_];
__device__ __align__(16) __nv_bfloat16 g_wqh[(size_t)D_*D_];
__device__ __align__(16) __nv_bfloat16 g_wql[(size_t)D_*D_];
__device__ __align__(16) __nv_bfloat16 g_wkh[(size_t)KVD_*D_];
__device__ __align__(16) __nv_bfloat16 g_wkl[(size_t)KVD_*D_];
__device__ __align__(16) __nv_bfloat16 g_wvh[(size_t)KVD_*D_];
__device__ __align__(16) __nv_bfloat16 g_wvl[(size_t)KVD_*D_];
__device__ __align__(16) __nv_bfloat16 g_woh[(size_t)D_*D_];
__device__ __align__(16) __nv_bfloat16 g_wol[(size_t)D_*D_];

// ================= helpers =================
static __device__ __forceinline__ unsigned int smem_u32(const void* p) {
    unsigned int a;
    asm("{ .reg .u64 t; cvta.to.shared.u64 t, %1; cvt.u32.u64 %0, t; }"
        : "=r"(a) : "l"(p));
    return a;
}

static __device__ __forceinline__ void ldm_x4(unsigned int* r, unsigned int addr) {
    asm volatile("ldmatrix.sync.aligned.m8n8.x4.shared.b16 {%0,%1,%2,%3}, [%4];"
                 : "=r"(r[0]), "=r"(r[1]), "=r"(r[2]), "=r"(r[3]) : "r"(addr));
}
static __device__ __forceinline__ void ldm_x2(unsigned int* r, unsigned int addr) {
    asm volatile("ldmatrix.sync.aligned.m8n8.x2.shared.b16 {%0,%1}, [%2];"
                 : "=r"(r[0]), "=r"(r[1]) : "r"(addr));
}
static __device__ __forceinline__ void mma_bf16(float* d, const unsigned int* a,
                                                const unsigned int* b) {
    asm volatile(
        "mma.sync.aligned.m16n8k16.row.col.f32.bf16.bf16.f32 "
        "{%0,%1,%2,%3}, {%4,%5,%6,%7}, {%8,%9}, {%0,%1,%2,%3};"
        : "+f"(d[0]), "+f"(d[1]), "+f"(d[2]), "+f"(d[3])
        : "r"(a[0]), "r"(a[1]), "r"(a[2]), "r"(a[3]), "r"(b[0]), "r"(b[1]));
}

// ================= split fp32 -> bf16 hi/lo =================
__global__ __launch_bounds__(256) void split_bf16(
    const float* __restrict__ in, __nv_bfloat16* __restrict__ hi,
    __nv_bfloat16* __restrict__ lo, int n4)
{
    int i = blockIdx.x * 256 + threadIdx.x;
    if (i >= n4) return;
    float4 v = ((const float4*)in)[i];
    __nv_bfloat16 h0 = __float2bfloat16(v.x);
    __nv_bfloat16 h1 = __float2bfloat16(v.y);
    __nv_bfloat16 h2 = __float2bfloat16(v.z);
    __nv_bfloat16 h3 = __float2bfloat16(v.w);
    __nv_bfloat16 l0 = __float2bfloat16(v.x - __bfloat162float(h0));
    __nv_bfloat16 l1 = __float2bfloat16(v.y - __bfloat162float(h1));
    __nv_bfloat16 l2 = __float2bfloat16(v.z - __bfloat162float(h2));
    __nv_bfloat16 l3 = __float2bfloat16(v.w - __bfloat162float(h3));
    unsigned int ph0 = ((unsigned int)__bfloat16_as_ushort(h1) << 16) | (unsigned int)__bfloat16_as_ushort(h0);
    unsigned int ph1 = ((unsigned int)__bfloat16_as_ushort(h3) << 16) | (unsigned int)__bfloat16_as_ushort(h2);
    unsigned int pl0 = ((unsigned int)__bfloat16_as_ushort(l1) << 16) | (unsigned int)__bfloat16_as_ushort(l0);
    unsigned int pl1 = ((unsigned int)__bfloat16_as_ushort(l3) << 16) | (unsigned int)__bfloat16_as_ushort(l2);
    ((unsigned int*)hi)[2*i]   = ph0;
    ((unsigned int*)hi)[2*i+1] = ph1;
    ((unsigned int*)lo)[2*i]   = pl0;
    ((unsigned int*)lo)[2*i+1] = pl1;
}

// ================= mma.sync split-bf16 GEMM =================
// C[M,N] = alpha * (Ah+Al)[M,K] @ (Bh+Bl)[N,K]^T   (dropping Al*Bl)
// 128x128 CTA tile, BK=64, 8 warps (warp tile 64x32), 3 accumulate passes.
#define SA 72   // padded bf16 stride (144B): conflict-free ldmatrix
#define GEMM_SMEM_BYTES (2 * 128 * SA * 2)

__global__ __launch_bounds__(256) void gemm_tc(
    const __nv_bfloat16* __restrict__ Ah, const __nv_bfloat16* __restrict__ Al,
    const __nv_bfloat16* __restrict__ Bh, const __nv_bfloat16* __restrict__ Bl,
    float* __restrict__ C, int M, int N, int K, float alpha)
{
    extern __shared__ __nv_bfloat16 gsm[];
    __nv_bfloat16* As = gsm;                 // [128][SA]
    __nv_bfloat16* Bs = gsm + 128 * SA;      // [128][SA]
    const unsigned int baseA = smem_u32(As);
    const unsigned int baseB = smem_u32(Bs);

    const int tid  = threadIdx.x;
    const int wid  = tid >> 5;
    const int lane = tid & 31;
    const int warp_m = wid >> 2;             // 0..1  -> rows warp_m*64
    const int warp_n = wid & 3;              // 0..3  -> cols warp_n*32
    const int m0 = blockIdx.y * 128;
    const int n0 = blockIdx.x * 128;

    float acc[4][4][4];
#pragma unroll
    for (int i = 0; i < 4; i++)
#pragma unroll
        for (int j = 0; j < 4; j++)
#pragma unroll
            for (int t = 0; t < 4; t++) acc[i][j][t] = 0.f;

    // fragment smem addresses (constant across iterations)
    // A frag (mf, kf): row = warp_m*64 + mf*16 + (lane&15), col = kf*16 + (lane>>4)*8
    unsigned int a_addr0 = baseA + (unsigned int)(((warp_m * 64 + (lane & 15)) * SA
                                                   + ((lane >> 4) << 3)) * 2);
    // B frag (nf, kf): row = warp_n*32 + nf*8 + (lane&7), col = kf*16 + ((lane>>3)&1)*8
    unsigned int b_addr0 = baseB + (unsigned int)(((warp_n * 32 + (lane & 7)) * SA
                                                   + (((lane >> 3) & 1) << 3)) * 2);

    const __nv_bfloat16* Aps[3]; const __nv_bfloat16* Bps[3];
    Aps[0] = Ah; Bps[0] = Bh;
    Aps[1] = Ah; Bps[1] = Bl;
    Aps[2] = Al; Bps[2] = Bh;

    const int nk = K / 64;

    for (int pass = 0; pass < 3; pass++) {
        const __nv_bfloat16* Ap = Aps[pass];
        const __nv_bfloat16* Bp = Bps[pass];
        for (int kt = 0; kt < nk; kt++) {
            const int k0 = kt * 64;
            // load A,B tiles: 128 rows x 64 cols each; 8 slots of 8 bf16 per row
#pragma unroll
            for (int it = 0; it < 4; it++) {
                int i = tid + it * 256;       // 0..1023
                int r = i >> 3, sl = i & 7;
                *(float4*)&As[r * SA + sl * 8] =
                    *(const float4*)(Ap + (size_t)(m0 + r) * K + k0 + sl * 8);
                *(float4*)&Bs[r * SA + sl * 8] =
                    *(const float4*)(Bp + (size_t)(n0 + r) * K + k0 + sl * 8);
            }
            __syncthreads();

#pragma unroll
            for (int kf = 0; kf < 4; kf++) {
                unsigned int af[4][4], bf[4][2];
#pragma unroll
                for (int mf = 0; mf < 4; mf++)
                    ldm_x4(af[mf], a_addr0 + (unsigned int)((mf * 16 * SA + kf * 16) * 2));
#pragma unroll
                for (int nf = 0; nf < 4; nf++)
                    ldm_x2(bf[nf], b_addr0 + (unsigned int)((nf * 8 * SA + kf * 16) * 2));
#pragma unroll
                for (int mf = 0; mf < 4; mf++)
#pragma unroll
                    for (int nf = 0; nf < 4; nf++)
                        mma_bf16(acc[mf][nf], af[mf], bf[nf]);
            }
            __syncthreads();
        }
    }

    // epilogue: c frag layout m16n8 -> rows lane>>2 (+8), cols (lane&3)*2 (+1)
    const int rb = m0 + warp_m * 64 + (lane >> 2);
    const int cb = n0 + warp_n * 32 + ((lane & 3) << 1);
#pragma unroll
    for (int mf = 0; mf < 4; mf++) {
#pragma unroll
        for (int nf = 0; nf < 4; nf++) {
            float2 v0, v1;
            v0.x = alpha * acc[mf][nf][0];
            v0.y = alpha * acc[mf][nf][1];
            v1.x = alpha * acc[mf][nf][2];
            v1.y = alpha * acc[mf][nf][3];
            *(float2*)&C[(size_t)(rb + mf * 16)     * N + cb + nf * 8] = v0;
            *(float2*)&C[(size_t)(rb + mf * 16 + 8) * N + cb + nf * 8] = v1;
        }
    }
}

// ============================================================
// Fused flash attention + relative-position bias (fp32, as in R3).
// ============================================================
#define QS(d,qq) qsT[(d)*68 + (qq)]
#define KS(d,cc) ksT[(d)*68 + (cc)]
#define VS(cc,d) vsm[(cc)*68 + (d)]
#define PS(rr,cc) psm[(rr)*68 + (cc)]
#define QE(rr,p) qem[(rr)*256 + (p)]

#define ATTN_SMEM_BYTES ((4*64*68 + 64*256) * 4)

__global__ __launch_bounds__(256) void attn_kernel(
    const float* __restrict__ q, const float* __restrict__ k,
    const float* __restrict__ v, const float* __restrict__ E,
    float* __restrict__ o)
{
    extern __shared__ float attn_sm[];
    float* qsT = attn_sm;
    float* ksT = qsT + 64*68;
    float* vsm = ksT + 64*68;
    float* psm = vsm + 64*68;
    float* qem = psm + 64*68;

    const int tid = threadIdx.x;
    const int tx = tid & 15, ty = tid >> 4;
    const int r0  = ty << 2;
    const int c0  = tx << 2;
    const int q0 = blockIdx.x * 64;
    const int h  = blockIdx.y;
    const int b  = blockIdx.z;
    const int g  = h >> 2;

    const float* qbase = q + ((size_t)(b * T_ + q0)) * D_ + h * HD_;
    for (int idx = tid; idx < 64 * 64; idx += 256) {
        int r = idx >> 6, d = idx & 63;
        QS(d, r) = qbase[(size_t)r * D_ + d];
    }
    __syncthreads();

    for (int p0 = 0; p0 < NREL; p0 += 64) {
        int np = NREL - p0; if (np > 64) np = 64;
        for (int idx = tid; idx < np * 64; idx += 256) {
            int p = idx >> 6, d = idx & 63;
            KS(d, p) = E[(size_t)(p0 + p) * HD_ + d];
        }
        __syncthreads();
        float aq[4][4];
#pragma unroll
        for (int i = 0; i < 4; i++)
#pragma unroll
            for (int j = 0; j < 4; j++) aq[i][j] = 0.f;
#pragma unroll 8
        for (int d = 0; d < 64; d++) {
            float4 a4 = *(const float4*)&QS(d, r0);
            float4 e4 = *(const float4*)&KS(d, c0);
            float ar[4] = {a4.x, a4.y, a4.z, a4.w};
            float er[4] = {e4.x, e4.y, e4.z, e4.w};
#pragma unroll
            for (int i = 0; i < 4; i++)
#pragma unroll
                for (int j = 0; j < 4; j++)
                    aq[i][j] += ar[i] * er[j];
        }
#pragma unroll
        for (int i = 0; i < 4; i++)
#pragma unroll
            for (int j = 0; j < 4; j++)
                if (c0 + j < np) QE(r0 + i, p0 + c0 + j) = aq[i][j];
        __syncthreads();
    }

    float m_r[4], l_r[4], acc[4][4];
#pragma unroll
    for (int i = 0; i < 4; i++) { m_r[i] = -1e30f; l_r[i] = 0.f; }
#pragma unroll
    for (int i = 0; i < 4; i++)
#pragma unroll
        for (int j = 0; j < 4; j++) acc[i][j] = 0.f;

    const float* kbase = k + (size_t)b * T_ * KVD_ + g * HD_;
    const float* vbase = v + (size_t)b * T_ * KVD_ + g * HD_;

    for (int kt = 0; kt < T_; kt += 64) {
        for (int idx = tid; idx < 64 * 64; idx += 256) {
            int c = idx >> 6, d = idx & 63;
            KS(d, c) = kbase[(size_t)(kt + c) * KVD_ + d];
            VS(c, d) = vbase[(size_t)(kt + c) * KVD_ + d];
        }
        __syncthreads();

        float s[4][4];
#pragma unroll
        for (int i = 0; i < 4; i++)
#pragma unroll
            for (int j = 0; j < 4; j++) s[i][j] = 0.f;
#pragma unroll 8
        for (int kk = 0; kk < 64; kk++) {
            float4 a4 = *(const float4*)&QS(kk, r0);
            float4 b4 = *(const float4*)&KS(kk, c0);
            float ar[4] = {a4.x, a4.y, a4.z, a4.w};
            float br[4] = {b4.x, b4.y, b4.z, b4.w};
#pragma unroll
            for (int i = 0; i < 4; i++)
#pragma unroll
                for (int j = 0; j < 4; j++)
                    s[i][j] += ar[i] * br[j];
        }

#pragma unroll
        for (int i = 0; i < 4; i++) {
            int qg = q0 + r0 + i;
#pragma unroll
            for (int j = 0; j < 4; j++) {
                int dlt = qg - (kt + c0 + j);
                dlt = max(-127, min(127, dlt));
                s[i][j] += QE(r0 + i, dlt + 127);
            }
        }

#pragma unroll
        for (int i = 0; i < 4; i++) {
            float tm = fmaxf(fmaxf(s[i][0], s[i][1]), fmaxf(s[i][2], s[i][3]));
            tm = fmaxf(tm, __shfl_xor_sync(0xffffffffu, tm, 1));
            tm = fmaxf(tm, __shfl_xor_sync(0xffffffffu, tm, 2));
            tm = fmaxf(tm, __shfl_xor_sync(0xffffffffu, tm, 4));
            tm = fmaxf(tm, __shfl_xor_sync(0xffffffffu, tm, 8));
            float mnew = fmaxf(m_r[i], tm);
            float scl = __expf(m_r[i] - mnew);
            float ls = 0.f;
#pragma unroll
            for (int j = 0; j < 4; j++) {
                s[i][j] = __expf(s[i][j] - mnew);
                ls += s[i][j];
            }
            ls += __shfl_xor_sync(0xffffffffu, ls, 1);
            ls += __shfl_xor_sync(0xffffffffu, ls, 2);
            ls += __shfl_xor_sync(0xffffffffu, ls, 4);
            ls += __shfl_xor_sync(0xffffffffu, ls, 8);
            l_r[i] = l_r[i] * scl + ls;
            m_r[i] = mnew;
#pragma unroll
            for (int j = 0; j < 4; j++) acc[i][j] *= scl;
            *(float4*)&PS(r0 + i, c0) = make_float4(s[i][0], s[i][1], s[i][2], s[i][3]);
        }
        __syncthreads();

#pragma unroll 4
        for (int kk = 0; kk < 64; kk++) {
            float pa[4];
#pragma unroll
            for (int i = 0; i < 4; i++) pa[i] = PS(r0 + i, kk);
            float4 v4 = *(const float4*)&VS(kk, c0);
            float vr[4] = {v4.x, v4.y, v4.z, v4.w};
#pragma unroll
            for (int i = 0; i < 4; i++)
#pragma unroll
                for (int j = 0; j < 4; j++)
                    acc[i][j] += pa[i] * vr[j];
        }
        __syncthreads();
    }

    float* obase = o + ((size_t)(b * T_ + q0)) * D_ + h * HD_;
#pragma unroll
    for (int i = 0; i < 4; i++) {
        float inv = 1.0f / l_r[i];
        float4 o4 = make_float4(acc[i][0] * inv, acc[i][1] * inv,
                                acc[i][2] * inv, acc[i][3] * inv);
        *(float4*)&obase[(size_t)(r0 + i) * D_ + c0] = o4;
    }
}

// ============================================================
extern "C" void kernel_launch(void* const* d_in, const int* in_sizes, int n_in,
                              void* d_out, int out_size)
{
    const float* x  = (const float*)d_in[0];
    const float* Wq = (const float*)d_in[1];
    const float* Wk = (const float*)d_in[2];
    const float* Wv = (const float*)d_in[3];
    const float* Wo = (const float*)d_in[4];
    const float* E  = (const float*)d_in[5];
    float* out = (float*)d_out;

    float* qp = 0; float* kp = 0; float* vp = 0; float* op = 0;
    cudaGetSymbolAddress((void**)&qp, g_q);
    cudaGetSymbolAddress((void**)&kp, g_k);
    cudaGetSymbolAddress((void**)&vp, g_v);
    cudaGetSymbolAddress((void**)&op, g_o);

    __nv_bfloat16* xh = 0;  __nv_bfloat16* xl = 0;
    __nv_bfloat16* oh = 0;  __nv_bfloat16* ol = 0;
    __nv_bfloat16* wqh = 0; __nv_bfloat16* wql = 0;
    __nv_bfloat16* wkh = 0; __nv_bfloat16* wkl = 0;
    __nv_bfloat16* wvh = 0; __nv_bfloat16* wvl = 0;
    __nv_bfloat16* woh = 0; __nv_bfloat16* wol = 0;
    cudaGetSymbolAddress((void**)&xh, g_xh);
    cudaGetSymbolAddress((void**)&xl, g_xl);
    cudaGetSymbolAddress((void**)&oh, g_oh);
    cudaGetSymbolAddress((void**)&ol, g_ol);
    cudaGetSymbolAddress((void**)&wqh, g_wqh);
    cudaGetSymbolAddress((void**)&wql, g_wql);
    cudaGetSymbolAddress((void**)&wkh, g_wkh);
    cudaGetSymbolAddress((void**)&wkl, g_wkl);
    cudaGetSymbolAddress((void**)&wvh, g_wvh);
    cudaGetSymbolAddress((void**)&wvl, g_wvl);
    cudaGetSymbolAddress((void**)&woh, g_woh);
    cudaGetSymbolAddress((void**)&wol, g_wol);

    cudaFuncSetAttribute(attn_kernel, cudaFuncAttributeMaxDynamicSharedMemorySize,
                         ATTN_SMEM_BYTES);
    cudaFuncSetAttribute(gemm_tc, cudaFuncAttributeMaxDynamicSharedMemorySize,
                         GEMM_SMEM_BYTES);

    const int M = 8192;                  // B_*T_
    const float qscale = 0.125f;         // 1/sqrt(64)

    int nx4 = (M * D_) / 4;
    int nw4 = (D_ * D_) / 4;
    int nk4 = (KVD_ * D_) / 4;

    split_bf16<<<(nx4 + 255) / 256, 256>>>(x, xh, xl, nx4);
    split_bf16<<<(nw4 + 255) / 256, 256>>>(Wq, wqh, wql, nw4);
    split_bf16<<<(nk4 + 255) / 256, 256>>>(Wk, wkh, wkl, nk4);
    split_bf16<<<(nk4 + 255) / 256, 256>>>(Wv, wvh, wvl, nk4);
    split_bf16<<<(nw4 + 255) / 256, 256>>>(Wo, woh, wol, nw4);

    dim3 gq(8, 64);    // D_/128, M/128
    dim3 gkv(2, 64);   // KVD_/128, M/128
    gemm_tc<<<gq,  256, GEMM_SMEM_BYTES>>>(xh, xl, wqh, wql, qp, M, D_, D_, qscale);
    gemm_tc<<<gkv, 256, GEMM_SMEM_BYTES>>>(xh, xl, wkh, wkl, kp, M, KVD_, D_, 1.0f);
    gemm_tc<<<gkv, 256, GEMM_SMEM_BYTES>>>(xh, xl, wvh, wvl, vp, M, KVD_, D_, 1.0f);

    dim3 ga(16, 16, 8);  // T_/64, H_, B_
    attn_kernel<<<ga, 256, ATTN_SMEM_BYTES>>>(qp, kp, vp, E, op);

    split_bf16<<<(nx4 + 255) / 256, 256>>>(op, oh, ol, nx4);
    gemm_tc<<<gq, 256, GEMM_SMEM_BYTES>>>(oh, ol, woh, wol, out, M, D_, D_, 1.0f);
}

// round 13
// speedup vs baseline: 2.3934x; 1.9863x over previous
#include <cuda_runtime.h>
#include <cuda_bf16.h>
#include <math.h>

#define B_  8
#define T_  1024
#define D_  1024
#define H_  16
#define G_  4
#define HD_ 64
#define KVD_ 256
#define NREL 255

// ================= scratch (static device arrays) =================
__device__ float g_q[(size_t)B_*T_*D_];
__device__ float g_k[(size_t)B_*T_*KVD_];
__device__ float g_v[(size_t)B_*T_*KVD_];
__device__ float g_o[(size_t)B_*T_*D_];

__device__ __align__(16) __nv_bfloat16 g_xh[(size_t)B_*T_*D_];
__device__ __align__(16) __nv_bfloat16 g_xl[(size_t)B_*T_*D_];
__device__ __align__(16) __nv_bfloat16 g_oh[(size_t)B_*T_*D_];
__device__ __align__(16) __nv_bfloat16 g_ol[(size_t)B_*T_*D_];
__device__ __align__(16) __nv_bfloat16 g_wqh[(size_t)D_*D_];
__device__ __align__(16) __nv_bfloat16 g_wql[(size_t)D_*D_];
__device__ __align__(16) __nv_bfloat16 g_wkh[(size_t)KVD_*D_];
__device__ __align__(16) __nv_bfloat16 g_wkl[(size_t)KVD_*D_];
__device__ __align__(16) __nv_bfloat16 g_wvh[(size_t)KVD_*D_];
__device__ __align__(16) __nv_bfloat16 g_wvl[(size_t)KVD_*D_];
__device__ __align__(16) __nv_bfloat16 g_woh[(size_t)D_*D_];
__device__ __align__(16) __nv_bfloat16 g_wol[(size_t)D_*D_];

// ================= helpers =================
static __device__ __forceinline__ unsigned int smem_u32(const void* p) {
    unsigned int a;
    asm("{ .reg .u64 t; cvta.to.shared.u64 t, %1; cvt.u32.u64 %0, t; }"
        : "=r"(a) : "l"(p));
    return a;
}
static __device__ __forceinline__ void ldm_x4(unsigned int* r, unsigned int addr) {
    asm volatile("ldmatrix.sync.aligned.m8n8.x4.shared.b16 {%0,%1,%2,%3}, [%4];"
                 : "=r"(r[0]), "=r"(r[1]), "=r"(r[2]), "=r"(r[3]) : "r"(addr));
}
static __device__ __forceinline__ void ldm_x2(unsigned int* r, unsigned int addr) {
    asm volatile("ldmatrix.sync.aligned.m8n8.x2.shared.b16 {%0,%1}, [%2];"
                 : "=r"(r[0]), "=r"(r[1]) : "r"(addr));
}
static __device__ __forceinline__ void mma_bf16(float* d, const unsigned int* a,
                                                const unsigned int* b) {
    asm volatile(
        "mma.sync.aligned.m16n8k16.row.col.f32.bf16.bf16.f32 "
        "{%0,%1,%2,%3}, {%4,%5,%6,%7}, {%8,%9}, {%0,%1,%2,%3};"
        : "+f"(d[0]), "+f"(d[1]), "+f"(d[2]), "+f"(d[3])
        : "r"(a[0]), "r"(a[1]), "r"(a[2]), "r"(a[3]), "r"(b[0]), "r"(b[1]));
}
static __device__ __forceinline__ unsigned int pack_hi2(float a, float b) {
    __nv_bfloat16 h0 = __float2bfloat16(a);
    __nv_bfloat16 h1 = __float2bfloat16(b);
    return ((unsigned int)__bfloat16_as_ushort(h1) << 16) |
           (unsigned int)__bfloat16_as_ushort(h0);
}
static __device__ __forceinline__ unsigned int pack_lo2(float a, float b) {
    __nv_bfloat16 h0 = __float2bfloat16(a);
    __nv_bfloat16 h1 = __float2bfloat16(b);
    __nv_bfloat16 l0 = __float2bfloat16(a - __bfloat162float(h0));
    __nv_bfloat16 l1 = __float2bfloat16(b - __bfloat162float(h1));
    return ((unsigned int)__bfloat16_as_ushort(l1) << 16) |
           (unsigned int)__bfloat16_as_ushort(l0);
}

// ================= split fp32 -> bf16 hi/lo =================
__global__ __launch_bounds__(256) void split_bf16(
    const float* __restrict__ in, __nv_bfloat16* __restrict__ hi,
    __nv_bfloat16* __restrict__ lo, int n4)
{
    int i = blockIdx.x * 256 + threadIdx.x;
    if (i >= n4) return;
    float4 v = ((const float4*)in)[i];
    ((unsigned int*)hi)[2*i]   = pack_hi2(v.x, v.y);
    ((unsigned int*)hi)[2*i+1] = pack_hi2(v.z, v.w);
    ((unsigned int*)lo)[2*i]   = pack_lo2(v.x, v.y);
    ((unsigned int*)lo)[2*i+1] = pack_lo2(v.z, v.w);
}

// ================= mma.sync split-bf16 GEMM (fused 3-product) =================
// C[M,N] = alpha*(Ah*Bh + Ah*Bl + Al*Bh)[M,K]@[N,K]^T
// 128x128 CTA tile, BK=64, 8 warps (warp tile 64x32).
#define SA 72
#define GEMM_SMEM_BYTES (4 * 128 * SA * 2)

__global__ __launch_bounds__(256) void gemm_tc(
    const __nv_bfloat16* __restrict__ Ah, const __nv_bfloat16* __restrict__ Al,
    const __nv_bfloat16* __restrict__ Bh, const __nv_bfloat16* __restrict__ Bl,
    float* __restrict__ C, int M, int N, int K, float alpha)
{
    extern __shared__ __nv_bfloat16 gsm[];
    __nv_bfloat16* Ahs = gsm;
    __nv_bfloat16* Als = gsm + 128 * SA;
    __nv_bfloat16* Bhs = gsm + 2 * 128 * SA;
    __nv_bfloat16* Bls = gsm + 3 * 128 * SA;

    const int tid  = threadIdx.x;
    const int wid  = tid >> 5;
    const int lane = tid & 31;
    const int warp_m = wid >> 2;
    const int warp_n = wid & 3;
    const int m0 = blockIdx.y * 128;
    const int n0 = blockIdx.x * 128;

    float acc[4][4][4];
#pragma unroll
    for (int i = 0; i < 4; i++)
#pragma unroll
        for (int j = 0; j < 4; j++)
#pragma unroll
            for (int t = 0; t < 4; t++) acc[i][j][t] = 0.f;

    unsigned int aH = smem_u32(Ahs) + (unsigned int)(((warp_m*64 + (lane & 15))*SA + ((lane >> 4) << 3)) * 2);
    unsigned int aL = aH + (unsigned int)(128 * SA * 2);
    unsigned int bH = smem_u32(Bhs) + (unsigned int)(((warp_n*32 + (lane & 7))*SA + (((lane >> 3) & 1) << 3)) * 2);
    unsigned int bL = bH + (unsigned int)(128 * SA * 2);

    const int nk = K / 64;
    for (int kt = 0; kt < nk; kt++) {
        const int k0 = kt * 64;
#pragma unroll
        for (int t = 0; t < 4; t++) {
            int i = tid + t * 256;
            int r = i >> 3, sl = (i & 7) << 3;
            *(float4*)&Ahs[r*SA + sl] = *(const float4*)(Ah + (size_t)(m0 + r)*K + k0 + sl);
            *(float4*)&Als[r*SA + sl] = *(const float4*)(Al + (size_t)(m0 + r)*K + k0 + sl);
            *(float4*)&Bhs[r*SA + sl] = *(const float4*)(Bh + (size_t)(n0 + r)*K + k0 + sl);
            *(float4*)&Bls[r*SA + sl] = *(const float4*)(Bl + (size_t)(n0 + r)*K + k0 + sl);
        }
        __syncthreads();
#pragma unroll
        for (int kf = 0; kf < 4; kf++) {
            unsigned int afh[4][4], afl[4][4], bfh[4][2], bfl[4][2];
#pragma unroll
            for (int mf = 0; mf < 4; mf++) {
                ldm_x4(afh[mf], aH + (unsigned int)((mf*16*SA + kf*16) * 2));
                ldm_x4(afl[mf], aL + (unsigned int)((mf*16*SA + kf*16) * 2));
            }
#pragma unroll
            for (int nf = 0; nf < 4; nf++) {
                ldm_x2(bfh[nf], bH + (unsigned int)((nf*8*SA + kf*16) * 2));
                ldm_x2(bfl[nf], bL + (unsigned int)((nf*8*SA + kf*16) * 2));
            }
#pragma unroll
            for (int mf = 0; mf < 4; mf++)
#pragma unroll
                for (int nf = 0; nf < 4; nf++) {
                    mma_bf16(acc[mf][nf], afh[mf], bfh[nf]);
                    mma_bf16(acc[mf][nf], afh[mf], bfl[nf]);
                    mma_bf16(acc[mf][nf], afl[mf], bfh[nf]);
                }
        }
        __syncthreads();
    }

    const int rb = m0 + warp_m * 64 + (lane >> 2);
    const int cb = n0 + warp_n * 32 + ((lane & 3) << 1);
#pragma unroll
    for (int mf = 0; mf < 4; mf++) {
#pragma unroll
        for (int nf = 0; nf < 4; nf++) {
            float2 v0, v1;
            v0.x = alpha * acc[mf][nf][0]; v0.y = alpha * acc[mf][nf][1];
            v1.x = alpha * acc[mf][nf][2]; v1.y = alpha * acc[mf][nf][3];
            *(float2*)&C[(size_t)(rb + mf*16)     * N + cb + nf*8] = v0;
            *(float2*)&C[(size_t)(rb + mf*16 + 8) * N + cb + nf*8] = v1;
        }
    }
}

// ============================================================
// Tensor-core flash attention + relpos bias.
// q-tile 128, 8 warps; warp owns 16 q-rows x full 64 cols.
// ============================================================
#define AT_SA 72
// byte offsets in dynamic smem
#define OFF_QH   0
#define OFF_QL   18432
#define OFF_KH   36864
#define OFF_KL   46080
#define OFF_VTH  55296
#define OFF_VTL  64512
#define OFF_PH   73728
#define OFF_PL   92160
#define OFF_QEM  110592
#define ATTN_SMEM_BYTES 176128

__global__ __launch_bounds__(256) void attn_kernel(
    const float* __restrict__ q, const float* __restrict__ k,
    const float* __restrict__ v, const float* __restrict__ E,
    float* __restrict__ o)
{
    extern __shared__ char attn_sm[];
    __nv_bfloat16* qh  = (__nv_bfloat16*)(attn_sm + OFF_QH);
    __nv_bfloat16* ql  = (__nv_bfloat16*)(attn_sm + OFF_QL);
    __nv_bfloat16* kh  = (__nv_bfloat16*)(attn_sm + OFF_KH);
    __nv_bfloat16* kl  = (__nv_bfloat16*)(attn_sm + OFF_KL);
    __nv_bfloat16* vth = (__nv_bfloat16*)(attn_sm + OFF_VTH);
    __nv_bfloat16* vtl = (__nv_bfloat16*)(attn_sm + OFF_VTL);
    __nv_bfloat16* ph  = (__nv_bfloat16*)(attn_sm + OFF_PH);
    __nv_bfloat16* pl  = (__nv_bfloat16*)(attn_sm + OFF_PL);
    __nv_bfloat16* qem = (__nv_bfloat16*)(attn_sm + OFF_QEM);

    const int tid  = threadIdx.x;
    const int wid  = tid >> 5;
    const int lane = tid & 31;
    const int q0 = blockIdx.x * 128;
    const int h  = blockIdx.y;
    const int b  = blockIdx.z;
    const int g  = h >> 2;

    // ---- load Q tile (128 x 64), split to qh/ql ----
    const float* qbase = q + ((size_t)(b * T_ + q0)) * D_ + h * HD_;
#pragma unroll
    for (int t = 0; t < 8; t++) {
        int idx = tid + t * 256;           // 0..2047 float4
        int r = idx >> 4, c = (idx & 15) << 2;
        float4 vq = *(const float4*)(qbase + (size_t)r * D_ + c);
        *(unsigned int*)&qh[r*AT_SA + c]     = pack_hi2(vq.x, vq.y);
        *(unsigned int*)&qh[r*AT_SA + c + 2] = pack_hi2(vq.z, vq.w);
        *(unsigned int*)&ql[r*AT_SA + c]     = pack_lo2(vq.x, vq.y);
        *(unsigned int*)&ql[r*AT_SA + c + 2] = pack_lo2(vq.z, vq.w);
    }
    __syncthreads();

    // fragment smem addresses (R11-validated mappings)
    const unsigned int a_rowoff = (unsigned int)(((wid*16 + (lane & 15))*AT_SA + ((lane >> 4) << 3)) * 2);
    const unsigned int aQH = smem_u32(qh) + a_rowoff;
    const unsigned int aQL = smem_u32(ql) + a_rowoff;
    const unsigned int aPH = smem_u32(ph) + a_rowoff;
    const unsigned int aPL = smem_u32(pl) + a_rowoff;
    const unsigned int b_rowoff = (unsigned int)(((lane & 7)*AT_SA + (((lane >> 3) & 1) << 3)) * 2);
    const unsigned int bKH = smem_u32(kh) + b_rowoff;
    const unsigned int bKL = smem_u32(kl) + b_rowoff;
    const unsigned int bVH = smem_u32(vth) + b_rowoff;
    const unsigned int bVL = smem_u32(vtl) + b_rowoff;

    const int r0l = wid * 16 + (lane >> 2);    // local q row (and +8)

    // ---- qe table: qe[q][p] = Q[q]·E[p], 4 chunks of 64 p-rows via TC ----
    for (int ch = 0; ch < 4; ch++) {
#pragma unroll
        for (int t = 0; t < 4; t++) {
            int idx = tid + t * 256;       // 0..1023 float4 (64x64)
            int r = idx >> 4, c = (idx & 15) << 2;
            int p = ch * 64 + r;
            float4 ve;
            if (p < NREL) ve = *(const float4*)(E + (size_t)p * HD_ + c);
            else          ve = make_float4(0.f, 0.f, 0.f, 0.f);
            *(unsigned int*)&kh[r*AT_SA + c]     = pack_hi2(ve.x, ve.y);
            *(unsigned int*)&kh[r*AT_SA + c + 2] = pack_hi2(ve.z, ve.w);
        }
        __syncthreads();
        float qe_acc[8][4];
#pragma unroll
        for (int nf = 0; nf < 8; nf++)
#pragma unroll
            for (int t = 0; t < 4; t++) qe_acc[nf][t] = 0.f;
#pragma unroll
        for (int kf = 0; kf < 4; kf++) {
            unsigned int afh[4], afl[4];
            ldm_x4(afh, aQH + (unsigned int)(kf * 32));
            ldm_x4(afl, aQL + (unsigned int)(kf * 32));
#pragma unroll
            for (int nf = 0; nf < 8; nf++) {
                unsigned int bfr[2];
                ldm_x2(bfr, bKH + (unsigned int)((nf*8*AT_SA + kf*16) * 2));
                mma_bf16(qe_acc[nf], afh, bfr);
                mma_bf16(qe_acc[nf], afl, bfr);
            }
        }
        int cbase = ch * 64 + ((lane & 3) << 1);
#pragma unroll
        for (int nf = 0; nf < 8; nf++) {
            *(unsigned int*)&qem[r0l*256 + cbase + nf*8] = pack_hi2(qe_acc[nf][0], qe_acc[nf][1]);
            *(unsigned int*)&qem[(r0l+8)*256 + cbase + nf*8] = pack_hi2(qe_acc[nf][2], qe_acc[nf][3]);
        }
        __syncthreads();
    }

    // ---- online softmax state ----
    float m0 = -1e30f, m1 = -1e30f, l0 = 0.f, l1 = 0.f;
    float acc_o[8][4];
#pragma unroll
    for (int nf = 0; nf < 8; nf++)
#pragma unroll
        for (int t = 0; t < 4; t++) acc_o[nf][t] = 0.f;

    const float* kb = k + (size_t)b * T_ * KVD_ + g * HD_;
    const float* vb = v + (size_t)b * T_ * KVD_ + g * HD_;

    for (int kt = 0; kt < T_ / 64; kt++) {
        // ---- load K (split) and V (split + transpose) ----
#pragma unroll
        for (int t = 0; t < 4; t++) {
            int idx = tid + t * 256;       // 0..1023 float4 (64x64)
            int r = idx >> 4, c = (idx & 15) << 2;
            float4 kv = *(const float4*)(kb + (size_t)(kt*64 + r) * KVD_ + c);
            *(unsigned int*)&kh[r*AT_SA + c]     = pack_hi2(kv.x, kv.y);
            *(unsigned int*)&kh[r*AT_SA + c + 2] = pack_hi2(kv.z, kv.w);
            *(unsigned int*)&kl[r*AT_SA + c]     = pack_lo2(kv.x, kv.y);
            *(unsigned int*)&kl[r*AT_SA + c + 2] = pack_lo2(kv.z, kv.w);
            float4 vv = *(const float4*)(vb + (size_t)(kt*64 + r) * KVD_ + c);
            float vf[4] = {vv.x, vv.y, vv.z, vv.w};
#pragma unroll
            for (int j = 0; j < 4; j++) {
                __nv_bfloat16 hv = __float2bfloat16(vf[j]);
                __nv_bfloat16 lv = __float2bfloat16(vf[j] - __bfloat162float(hv));
                vth[(c + j)*AT_SA + r] = hv;
                vtl[(c + j)*AT_SA + r] = lv;
            }
        }
        __syncthreads();

        // ---- scores S = Q K^T (3-pass split) ----
        float s[8][4];
#pragma unroll
        for (int nf = 0; nf < 8; nf++)
#pragma unroll
            for (int t = 0; t < 4; t++) s[nf][t] = 0.f;
#pragma unroll
        for (int kf = 0; kf < 4; kf++) {
            unsigned int afh[4], afl[4];
            ldm_x4(afh, aQH + (unsigned int)(kf * 32));
            ldm_x4(afl, aQL + (unsigned int)(kf * 32));
#pragma unroll
            for (int nf = 0; nf < 8; nf++) {
                unsigned int bfh[2], bfl[2];
                ldm_x2(bfh, bKH + (unsigned int)((nf*8*AT_SA + kf*16) * 2));
                ldm_x2(bfl, bKL + (unsigned int)((nf*8*AT_SA + kf*16) * 2));
                mma_bf16(s[nf], afh, bfh);
                mma_bf16(s[nf], afh, bfl);
                mma_bf16(s[nf], afl, bfh);
            }
        }

        // ---- relpos bias from qe table ----
        const int qg0 = q0 + r0l;
#pragma unroll
        for (int nf = 0; nf < 8; nf++) {
            int kgb = kt*64 + nf*8 + ((lane & 3) << 1);
#pragma unroll
            for (int t = 0; t < 4; t++) {
                int row = r0l + ((t >> 1) << 3);
                int qg  = qg0 + ((t >> 1) << 3);
                int kg  = kgb + (t & 1);
                int dlt = qg - kg;
                dlt = max(-127, min(127, dlt)) + 127;
                s[nf][t] += __bfloat162float(qem[row*256 + dlt]);
            }
        }

        // ---- online softmax (rows r0l and r0l+8; quad-lane shfl) ----
        float tm0 = -1e30f, tm1 = -1e30f;
#pragma unroll
        for (int nf = 0; nf < 8; nf++) {
            tm0 = fmaxf(tm0, fmaxf(s[nf][0], s[nf][1]));
            tm1 = fmaxf(tm1, fmaxf(s[nf][2], s[nf][3]));
        }
        tm0 = fmaxf(tm0, __shfl_xor_sync(0xffffffffu, tm0, 1));
        tm0 = fmaxf(tm0, __shfl_xor_sync(0xffffffffu, tm0, 2));
        tm1 = fmaxf(tm1, __shfl_xor_sync(0xffffffffu, tm1, 1));
        tm1 = fmaxf(tm1, __shfl_xor_sync(0xffffffffu, tm1, 2));
        float mn0 = fmaxf(m0, tm0), mn1 = fmaxf(m1, tm1);
        float sc0 = __expf(m0 - mn0), sc1 = __expf(m1 - mn1);
        float ls0 = 0.f, ls1 = 0.f;
#pragma unroll
        for (int nf = 0; nf < 8; nf++) {
            s[nf][0] = __expf(s[nf][0] - mn0);
            s[nf][1] = __expf(s[nf][1] - mn0);
            s[nf][2] = __expf(s[nf][2] - mn1);
            s[nf][3] = __expf(s[nf][3] - mn1);
            ls0 += s[nf][0] + s[nf][1];
            ls1 += s[nf][2] + s[nf][3];
        }
        ls0 += __shfl_xor_sync(0xffffffffu, ls0, 1);
        ls0 += __shfl_xor_sync(0xffffffffu, ls0, 2);
        ls1 += __shfl_xor_sync(0xffffffffu, ls1, 1);
        ls1 += __shfl_xor_sync(0xffffffffu, ls1, 2);
        l0 = l0 * sc0 + ls0;  m0 = mn0;
        l1 = l1 * sc1 + ls1;  m1 = mn1;
#pragma unroll
        for (int nf = 0; nf < 8; nf++) {
            acc_o[nf][0] *= sc0; acc_o[nf][1] *= sc0;
            acc_o[nf][2] *= sc1; acc_o[nf][3] *= sc1;
        }

        // ---- store P split into warp-private stripe ----
        {
            int cc = ((lane & 3) << 1);
#pragma unroll
            for (int nf = 0; nf < 8; nf++) {
                int c0i = cc + nf*8;
                *(unsigned int*)&ph[r0l*AT_SA + c0i]     = pack_hi2(s[nf][0], s[nf][1]);
                *(unsigned int*)&pl[r0l*AT_SA + c0i]     = pack_lo2(s[nf][0], s[nf][1]);
                *(unsigned int*)&ph[(r0l+8)*AT_SA + c0i] = pack_hi2(s[nf][2], s[nf][3]);
                *(unsigned int*)&pl[(r0l+8)*AT_SA + c0i] = pack_lo2(s[nf][2], s[nf][3]);
            }
        }
        __syncwarp();

        // ---- acc_o += P V (3-pass split) ----
#pragma unroll
        for (int kf = 0; kf < 4; kf++) {
            unsigned int aph[4], apl[4];
            ldm_x4(aph, aPH + (unsigned int)(kf * 32));
            ldm_x4(apl, aPL + (unsigned int)(kf * 32));
#pragma unroll
            for (int nf = 0; nf < 8; nf++) {
                unsigned int bvh[2], bvl[2];
                ldm_x2(bvh, bVH + (unsigned int)((nf*8*AT_SA + kf*16) * 2));
                ldm_x2(bvl, bVL + (unsigned int)((nf*8*AT_SA + kf*16) * 2));
                mma_bf16(acc_o[nf], aph, bvh);
                mma_bf16(acc_o[nf], aph, bvl);
                mma_bf16(acc_o[nf], apl, bvh);
            }
        }
        __syncthreads();
    }

    // ---- epilogue ----
    float inv0 = 1.f / l0, inv1 = 1.f / l1;
    float* ob0 = o + ((size_t)(b * T_ + q0 + r0l)) * D_ + h * HD_;
    float* ob1 = ob0 + (size_t)8 * D_;
#pragma unroll
    for (int nf = 0; nf < 8; nf++) {
        int cc = nf*8 + ((lane & 3) << 1);
        float2 v0, v1;
        v0.x = acc_o[nf][0] * inv0; v0.y = acc_o[nf][1] * inv0;
        v1.x = acc_o[nf][2] * inv1; v1.y = acc_o[nf][3] * inv1;
        *(float2*)&ob0[cc] = v0;
        *(float2*)&ob1[cc] = v1;
    }
}

// ============================================================
extern "C" void kernel_launch(void* const* d_in, const int* in_sizes, int n_in,
                              void* d_out, int out_size)
{
    const float* x  = (const float*)d_in[0];
    const float* Wq = (const float*)d_in[1];
    const float* Wk = (const float*)d_in[2];
    const float* Wv = (const float*)d_in[3];
    const float* Wo = (const float*)d_in[4];
    const float* E  = (const float*)d_in[5];
    float* out = (float*)d_out;

    float* qp = 0; float* kp = 0; float* vp = 0; float* op = 0;
    cudaGetSymbolAddress((void**)&qp, g_q);
    cudaGetSymbolAddress((void**)&kp, g_k);
    cudaGetSymbolAddress((void**)&vp, g_v);
    cudaGetSymbolAddress((void**)&op, g_o);

    __nv_bfloat16* xh = 0;  __nv_bfloat16* xl = 0;
    __nv_bfloat16* oh = 0;  __nv_bfloat16* ol = 0;
    __nv_bfloat16* wqh = 0; __nv_bfloat16* wql = 0;
    __nv_bfloat16* wkh = 0; __nv_bfloat16* wkl = 0;
    __nv_bfloat16* wvh = 0; __nv_bfloat16* wvl = 0;
    __nv_bfloat16* woh = 0; __nv_bfloat16* wol = 0;
    cudaGetSymbolAddress((void**)&xh, g_xh);
    cudaGetSymbolAddress((void**)&xl, g_xl);
    cudaGetSymbolAddress((void**)&oh, g_oh);
    cudaGetSymbolAddress((void**)&ol, g_ol);
    cudaGetSymbolAddress((void**)&wqh, g_wqh);
    cudaGetSymbolAddress((void**)&wql, g_wql);
    cudaGetSymbolAddress((void**)&wkh, g_wkh);
    cudaGetSymbolAddress((void**)&wkl, g_wkl);
    cudaGetSymbolAddress((void**)&wvh, g_wvh);
    cudaGetSymbolAddress((void**)&wvl, g_wvl);
    cudaGetSymbolAddress((void**)&woh, g_woh);
    cudaGetSymbolAddress((void**)&wol, g_wol);

    cudaFuncSetAttribute(attn_kernel, cudaFuncAttributeMaxDynamicSharedMemorySize,
                         ATTN_SMEM_BYTES);
    cudaFuncSetAttribute(gemm_tc, cudaFuncAttributeMaxDynamicSharedMemorySize,
                         GEMM_SMEM_BYTES);

    const int M = 8192;                  // B_*T_
    const float qscale = 0.125f;         // 1/sqrt(64)

    int nx4 = (M * D_) / 4;
    int nw4 = (D_ * D_) / 4;
    int nk4 = (KVD_ * D_) / 4;

    split_bf16<<<(nx4 + 255) / 256, 256>>>(x, xh, xl, nx4);
    split_bf16<<<(nw4 + 255) / 256, 256>>>(Wq, wqh, wql, nw4);
    split_bf16<<<(nk4 + 255) / 256, 256>>>(Wk, wkh, wkl, nk4);
    split_bf16<<<(nk4 + 255) / 256, 256>>>(Wv, wvh, wvl, nk4);
    split_bf16<<<(nw4 + 255) / 256, 256>>>(Wo, woh, wol, nw4);

    dim3 gq(8, 64);    // D_/128, M/128
    dim3 gkv(2, 64);   // KVD_/128, M/128
    gemm_tc<<<gq,  256, GEMM_SMEM_BYTES>>>(xh, xl, wqh, wql, qp, M, D_, D_, qscale);
    gemm_tc<<<gkv, 256, GEMM_SMEM_BYTES>>>(xh, xl, wkh, wkl, kp, M, KVD_, D_, 1.0f);
    gemm_tc<<<gkv, 256, GEMM_SMEM_BYTES>>>(xh, xl, wvh, wvl, vp, M, KVD_, D_, 1.0f);

    dim3 ga(8, 16, 8);  // T_/128, H_, B_
    attn_kernel<<<ga, 256, ATTN_SMEM_BYTES>>>(qp, kp, vp, E, op);

    split_bf16<<<(nx4 + 255) / 256, 256>>>(op, oh, ol, nx4);
    gemm_tc<<<gq, 256, GEMM_SMEM_BYTES>>>(oh, ol, woh, wol, out, M, D_, D_, 1.0f);
}

// round 15
// speedup vs baseline: 2.6526x; 1.1083x over previous
#include <cuda_runtime.h>
#include <cuda_bf16.h>
#include <math.h>

#define B_  8
#define T_  1024
#define D_  1024
#define H_  16
#define G_  4
#define HD_ 64
#define KVD_ 256
#define NREL 255

// ================= scratch (static device arrays) =================
__device__ __align__(16) __nv_bfloat16 g_xh[(size_t)B_*T_*D_];
__device__ __align__(16) __nv_bfloat16 g_xl[(size_t)B_*T_*D_];
__device__ __align__(16) __nv_bfloat16 g_qh[(size_t)B_*T_*D_];
__device__ __align__(16) __nv_bfloat16 g_ql[(size_t)B_*T_*D_];
__device__ __align__(16) __nv_bfloat16 g_kh[(size_t)B_*T_*KVD_];
__device__ __align__(16) __nv_bfloat16 g_kl[(size_t)B_*T_*KVD_];
__device__ __align__(16) __nv_bfloat16 g_vh[(size_t)B_*T_*KVD_];
__device__ __align__(16) __nv_bfloat16 g_vl[(size_t)B_*T_*KVD_];
__device__ __align__(16) __nv_bfloat16 g_oh[(size_t)B_*T_*D_];
__device__ __align__(16) __nv_bfloat16 g_ol[(size_t)B_*T_*D_];
__device__ __align__(16) __nv_bfloat16 g_wqh[(size_t)D_*D_];
__device__ __align__(16) __nv_bfloat16 g_wql[(size_t)D_*D_];
__device__ __align__(16) __nv_bfloat16 g_wkh[(size_t)KVD_*D_];
__device__ __align__(16) __nv_bfloat16 g_wkl[(size_t)KVD_*D_];
__device__ __align__(16) __nv_bfloat16 g_wvh[(size_t)KVD_*D_];
__device__ __align__(16) __nv_bfloat16 g_wvl[(size_t)KVD_*D_];
__device__ __align__(16) __nv_bfloat16 g_woh[(size_t)D_*D_];
__device__ __align__(16) __nv_bfloat16 g_wol[(size_t)D_*D_];

// ================= helpers =================
static __device__ __forceinline__ unsigned int smem_u32(const void* p) {
    unsigned int a;
    asm("{ .reg .u64 t; cvta.to.shared.u64 t, %1; cvt.u32.u64 %0, t; }"
        : "=r"(a) : "l"(p));
    return a;
}
static __device__ __forceinline__ void ldm_x4(unsigned int* r, unsigned int addr) {
    asm volatile("ldmatrix.sync.aligned.m8n8.x4.shared.b16 {%0,%1,%2,%3}, [%4];"
                 : "=r"(r[0]), "=r"(r[1]), "=r"(r[2]), "=r"(r[3]) : "r"(addr));
}
static __device__ __forceinline__ void ldm_x2(unsigned int* r, unsigned int addr) {
    asm volatile("ldmatrix.sync.aligned.m8n8.x2.shared.b16 {%0,%1}, [%2];"
                 : "=r"(r[0]), "=r"(r[1]) : "r"(addr));
}
static __device__ __forceinline__ void ldm_x2_trans(unsigned int* r, unsigned int addr) {
    asm volatile("ldmatrix.sync.aligned.m8n8.x2.trans.shared.b16 {%0,%1}, [%2];"
                 : "=r"(r[0]), "=r"(r[1]) : "r"(addr));
}
static __device__ __forceinline__ void mma_bf16(float* d, const unsigned int* a,
                                                const unsigned int* b) {
    asm volatile(
        "mma.sync.aligned.m16n8k16.row.col.f32.bf16.bf16.f32 "
        "{%0,%1,%2,%3}, {%4,%5,%6,%7}, {%8,%9}, {%0,%1,%2,%3};"
        : "+f"(d[0]), "+f"(d[1]), "+f"(d[2]), "+f"(d[3])
        : "r"(a[0]), "r"(a[1]), "r"(a[2]), "r"(a[3]), "r"(b[0]), "r"(b[1]));
}
static __device__ __forceinline__ unsigned int pack_hi2(float a, float b) {
    __nv_bfloat16 h0 = __float2bfloat16(a);
    __nv_bfloat16 h1 = __float2bfloat16(b);
    return ((unsigned int)__bfloat16_as_ushort(h1) << 16) |
           (unsigned int)__bfloat16_as_ushort(h0);
}
static __device__ __forceinline__ unsigned int pack_lo2(float a, float b) {
    __nv_bfloat16 h0 = __float2bfloat16(a);
    __nv_bfloat16 h1 = __float2bfloat16(b);
    __nv_bfloat16 l0 = __float2bfloat16(a - __bfloat162float(h0));
    __nv_bfloat16 l1 = __float2bfloat16(b - __bfloat162float(h1));
    return ((unsigned int)__bfloat16_as_ushort(l1) << 16) |
           (unsigned int)__bfloat16_as_ushort(l0);
}

// ================= split fp32 -> bf16 hi/lo (inputs only) =================
__global__ __launch_bounds__(256) void split_bf16(
    const float* __restrict__ in, __nv_bfloat16* __restrict__ hi,
    __nv_bfloat16* __restrict__ lo, int n4)
{
    int i = blockIdx.x * 256 + threadIdx.x;
    if (i >= n4) return;
    float4 v = ((const float4*)in)[i];
    ((unsigned int*)hi)[2*i]   = pack_hi2(v.x, v.y);
    ((unsigned int*)hi)[2*i+1] = pack_hi2(v.z, v.w);
    ((unsigned int*)lo)[2*i]   = pack_lo2(v.x, v.y);
    ((unsigned int*)lo)[2*i+1] = pack_lo2(v.z, v.w);
}

// ================= mma.sync split-bf16 GEMM (fused 3-product) =================
// 128x128 CTA tile, BK=64, 8 warps (warp tile 64x32).
#define SA 72
#define GEMM_SMEM_BYTES (4 * 128 * SA * 2)

// -------- mainloop shared by both epilogues --------
#define GEMM_BODY()                                                                     \
    extern __shared__ __nv_bfloat16 gsm[];                                              \
    __nv_bfloat16* Ahs = gsm;                                                           \
    __nv_bfloat16* Als = gsm + 128 * SA;                                                \
    __nv_bfloat16* Bhs = gsm + 2 * 128 * SA;                                            \
    __nv_bfloat16* Bls = gsm + 3 * 128 * SA;                                            \
    const int tid  = threadIdx.x;                                                       \
    const int wid  = tid >> 5;                                                          \
    const int lane = tid & 31;                                                          \
    const int warp_m = wid >> 2;                                                        \
    const int warp_n = wid & 3;                                                         \
    const int m0 = blockIdx.y * 128;                                                    \
    const int n0 = blockIdx.x * 128;                                                    \
    float acc[4][4][4];                                                                 \
    _Pragma("unroll")                                                                   \
    for (int i = 0; i < 4; i++)                                                         \
        _Pragma("unroll")                                                               \
        for (int j = 0; j < 4; j++)                                                     \
            _Pragma("unroll")                                                           \
            for (int t = 0; t < 4; t++) acc[i][j][t] = 0.f;                             \
    unsigned int aH = smem_u32(Ahs) + (unsigned int)(((warp_m*64 + (lane & 15))*SA + ((lane >> 4) << 3)) * 2); \
    unsigned int aL = aH + (unsigned int)(128 * SA * 2);                                \
    unsigned int bH = smem_u32(Bhs) + (unsigned int)(((warp_n*32 + (lane & 7))*SA + (((lane >> 3) & 1) << 3)) * 2); \
    unsigned int bL = bH + (unsigned int)(128 * SA * 2);                                \
    const int nk = K / 64;                                                              \
    for (int kt = 0; kt < nk; kt++) {                                                   \
        const int k0 = kt * 64;                                                         \
        _Pragma("unroll")                                                               \
        for (int t = 0; t < 4; t++) {                                                   \
            int i = tid + t * 256;                                                      \
            int r = i >> 3, sl = (i & 7) << 3;                                          \
            *(float4*)&Ahs[r*SA + sl] = *(const float4*)(Ah + (size_t)(m0 + r)*K + k0 + sl); \
            *(float4*)&Als[r*SA + sl] = *(const float4*)(Al + (size_t)(m0 + r)*K + k0 + sl); \
            *(float4*)&Bhs[r*SA + sl] = *(const float4*)(Bh + (size_t)(n0 + r)*K + k0 + sl); \
            *(float4*)&Bls[r*SA + sl] = *(const float4*)(Bl + (size_t)(n0 + r)*K + k0 + sl); \
        }                                                                               \
        __syncthreads();                                                                \
        _Pragma("unroll")                                                               \
        for (int kf = 0; kf < 4; kf++) {                                                \
            unsigned int afh[4][4], afl[4][4], bfh[4][2], bfl[4][2];                    \
            _Pragma("unroll")                                                           \
            for (int mf = 0; mf < 4; mf++) {                                            \
                ldm_x4(afh[mf], aH + (unsigned int)((mf*16*SA + kf*16) * 2));           \
                ldm_x4(afl[mf], aL + (unsigned int)((mf*16*SA + kf*16) * 2));           \
            }                                                                           \
            _Pragma("unroll")                                                           \
            for (int nf = 0; nf < 4; nf++) {                                            \
                ldm_x2(bfh[nf], bH + (unsigned int)((nf*8*SA + kf*16) * 2));            \
                ldm_x2(bfl[nf], bL + (unsigned int)((nf*8*SA + kf*16) * 2));            \
            }                                                                           \
            _Pragma("unroll")                                                           \
            for (int mf = 0; mf < 4; mf++)                                              \
                _Pragma("unroll")                                                       \
                for (int nf = 0; nf < 4; nf++) {                                        \
                    mma_bf16(acc[mf][nf], afh[mf], bfh[nf]);                            \
                    mma_bf16(acc[mf][nf], afh[mf], bfl[nf]);                            \
                    mma_bf16(acc[mf][nf], afl[mf], bfh[nf]);                            \
                }                                                                       \
        }                                                                               \
        __syncthreads();                                                                \
    }                                                                                   \
    const int rb = m0 + warp_m * 64 + (lane >> 2);                                      \
    const int cb = n0 + warp_n * 32 + ((lane & 3) << 1);

// fp32-output variant (final projection)
__global__ __launch_bounds__(256) void gemm_tc(
    const __nv_bfloat16* __restrict__ Ah, const __nv_bfloat16* __restrict__ Al,
    const __nv_bfloat16* __restrict__ Bh, const __nv_bfloat16* __restrict__ Bl,
    float* __restrict__ C, int M, int N, int K, float alpha)
{
    GEMM_BODY()
#pragma unroll
    for (int mf = 0; mf < 4; mf++) {
#pragma unroll
        for (int nf = 0; nf < 4; nf++) {
            float2 v0, v1;
            v0.x = alpha * acc[mf][nf][0]; v0.y = alpha * acc[mf][nf][1];
            v1.x = alpha * acc[mf][nf][2]; v1.y = alpha * acc[mf][nf][3];
            *(float2*)&C[(size_t)(rb + mf*16)     * N + cb + nf*8] = v0;
            *(float2*)&C[(size_t)(rb + mf*16 + 8) * N + cb + nf*8] = v1;
        }
    }
}

// bf16 split-output variant (q/k/v projections)
__global__ __launch_bounds__(256) void gemm_tc_split(
    const __nv_bfloat16* __restrict__ Ah, const __nv_bfloat16* __restrict__ Al,
    const __nv_bfloat16* __restrict__ Bh, const __nv_bfloat16* __restrict__ Bl,
    __nv_bfloat16* __restrict__ Chi, __nv_bfloat16* __restrict__ Clo,
    int M, int N, int K, float alpha)
{
    GEMM_BODY()
#pragma unroll
    for (int mf = 0; mf < 4; mf++) {
#pragma unroll
        for (int nf = 0; nf < 4; nf++) {
            float a0 = alpha * acc[mf][nf][0], a1 = alpha * acc[mf][nf][1];
            float a2 = alpha * acc[mf][nf][2], a3 = alpha * acc[mf][nf][3];
            size_t i0 = (size_t)(rb + mf*16)     * N + cb + nf*8;
            size_t i1 = (size_t)(rb + mf*16 + 8) * N + cb + nf*8;
            *(unsigned int*)&Chi[i0] = pack_hi2(a0, a1);
            *(unsigned int*)&Clo[i0] = pack_lo2(a0, a1);
            *(unsigned int*)&Chi[i1] = pack_hi2(a2, a3);
            *(unsigned int*)&Clo[i1] = pack_lo2(a2, a3);
        }
    }
}

// ============================================================
// Tensor-core flash attention + relpos bias; pre-split bf16 I/O.
// q-tile 128, 8 warps; warp owns 16 q-rows x full 64 cols.
// V kept row-major; B-frags via ldmatrix.trans.
// ============================================================
#define AT_SA 72
#define OFF_QH   0
#define OFF_QL   18432
#define OFF_KH   36864
#define OFF_KL   46080
#define OFF_VH   55296
#define OFF_VL   64512
#define OFF_PH   73728
#define OFF_PL   92160
#define OFF_QEM  110592
#define ATTN_SMEM_BYTES 176128

__global__ __launch_bounds__(256) void attn_kernel(
    const __nv_bfloat16* __restrict__ qhg, const __nv_bfloat16* __restrict__ qlg,
    const __nv_bfloat16* __restrict__ khg, const __nv_bfloat16* __restrict__ klg,
    const __nv_bfloat16* __restrict__ vhg, const __nv_bfloat16* __restrict__ vlg,
    const float* __restrict__ E,
    __nv_bfloat16* __restrict__ ohg, __nv_bfloat16* __restrict__ olg)
{
    extern __shared__ char attn_sm[];
    __nv_bfloat16* qh  = (__nv_bfloat16*)(attn_sm + OFF_QH);
    __nv_bfloat16* ql  = (__nv_bfloat16*)(attn_sm + OFF_QL);
    __nv_bfloat16* kh  = (__nv_bfloat16*)(attn_sm + OFF_KH);
    __nv_bfloat16* kl  = (__nv_bfloat16*)(attn_sm + OFF_KL);
    __nv_bfloat16* vh  = (__nv_bfloat16*)(attn_sm + OFF_VH);
    __nv_bfloat16* vl  = (__nv_bfloat16*)(attn_sm + OFF_VL);
    __nv_bfloat16* ph  = (__nv_bfloat16*)(attn_sm + OFF_PH);
    __nv_bfloat16* pl  = (__nv_bfloat16*)(attn_sm + OFF_PL);
    __nv_bfloat16* qem = (__nv_bfloat16*)(attn_sm + OFF_QEM);

    const int tid  = threadIdx.x;
    const int wid  = tid >> 5;
    const int lane = tid & 31;
    const int q0 = blockIdx.x * 128;
    const int h  = blockIdx.y;
    const int b  = blockIdx.z;
    const int g  = h >> 2;

    // ---- load Q tile (128 x 64 bf16 hi/lo), direct copies ----
    const __nv_bfloat16* qbh = qhg + ((size_t)(b * T_ + q0)) * D_ + h * HD_;
    const __nv_bfloat16* qbl = qlg + ((size_t)(b * T_ + q0)) * D_ + h * HD_;
#pragma unroll
    for (int t = 0; t < 4; t++) {
        int idx = tid + t * 256;           // 0..1023 float4 (128 rows x 8 slots)
        int r = idx >> 3, sl = (idx & 7) << 3;
        *(float4*)&qh[r*AT_SA + sl] = *(const float4*)(qbh + (size_t)r * D_ + sl);
        *(float4*)&ql[r*AT_SA + sl] = *(const float4*)(qbl + (size_t)r * D_ + sl);
    }
    __syncthreads();

    // fragment smem addresses (R11/R13-validated mappings)
    const unsigned int a_rowoff = (unsigned int)(((wid*16 + (lane & 15))*AT_SA + ((lane >> 4) << 3)) * 2);
    const unsigned int aQH = smem_u32(qh) + a_rowoff;
    const unsigned int aQL = smem_u32(ql) + a_rowoff;
    const unsigned int aPH = smem_u32(ph) + a_rowoff;
    const unsigned int aPL = smem_u32(pl) + a_rowoff;
    const unsigned int b_rowoff = (unsigned int)(((lane & 7)*AT_SA + (((lane >> 3) & 1) << 3)) * 2);
    const unsigned int bKH = smem_u32(kh) + b_rowoff;
    const unsigned int bKL = smem_u32(kl) + b_rowoff;
    // trans B-frag base for V[kv][d]: lanes address rows kv = (lane>>3&1)*8 + (lane&7)
    const unsigned int bt_rowoff = (unsigned int)(((((lane >> 3) & 1) * 8 + (lane & 7)) * AT_SA) * 2);
    const unsigned int bVH = smem_u32(vh) + bt_rowoff;
    const unsigned int bVL = smem_u32(vl) + bt_rowoff;

    const int r0l = wid * 16 + (lane >> 2);

    // ---- qe table: qe[q][p] = Q[q]·E[p] via TC, 4 chunks of 64 p-rows ----
    for (int ch = 0; ch < 4; ch++) {
#pragma unroll
        for (int t = 0; t < 4; t++) {
            int idx = tid + t * 256;
            int r = idx >> 4, c = (idx & 15) << 2;
            int p = ch * 64 + r;
            float4 ve;
            if (p < NREL) ve = *(const float4*)(E + (size_t)p * HD_ + c);
            else          ve = make_float4(0.f, 0.f, 0.f, 0.f);
            *(unsigned int*)&kh[r*AT_SA + c]     = pack_hi2(ve.x, ve.y);
            *(unsigned int*)&kh[r*AT_SA + c + 2] = pack_hi2(ve.z, ve.w);
        }
        __syncthreads();
        float qe_acc[8][4];
#pragma unroll
        for (int nf = 0; nf < 8; nf++)
#pragma unroll
            for (int t = 0; t < 4; t++) qe_acc[nf][t] = 0.f;
#pragma unroll
        for (int kf = 0; kf < 4; kf++) {
            unsigned int afh[4], afl[4];
            ldm_x4(afh, aQH + (unsigned int)(kf * 32));
            ldm_x4(afl, aQL + (unsigned int)(kf * 32));
#pragma unroll
            for (int nf = 0; nf < 8; nf++) {
                unsigned int bfr[2];
                ldm_x2(bfr, bKH + (unsigned int)((nf*8*AT_SA + kf*16) * 2));
                mma_bf16(qe_acc[nf], afh, bfr);
                mma_bf16(qe_acc[nf], afl, bfr);
            }
        }
        int cbase = ch * 64 + ((lane & 3) << 1);
#pragma unroll
        for (int nf = 0; nf < 8; nf++) {
            *(unsigned int*)&qem[r0l*256 + cbase + nf*8] = pack_hi2(qe_acc[nf][0], qe_acc[nf][1]);
            *(unsigned int*)&qem[(r0l+8)*256 + cbase + nf*8] = pack_hi2(qe_acc[nf][2], qe_acc[nf][3]);
        }
        __syncthreads();
    }

    // ---- online softmax state ----
    float m0 = -1e30f, m1 = -1e30f, l0 = 0.f, l1 = 0.f;
    float acc_o[8][4];
#pragma unroll
    for (int nf = 0; nf < 8; nf++)
#pragma unroll
        for (int t = 0; t < 4; t++) acc_o[nf][t] = 0.f;

    const __nv_bfloat16* kbh = khg + (size_t)b * T_ * KVD_ + g * HD_;
    const __nv_bfloat16* kbl = klg + (size_t)b * T_ * KVD_ + g * HD_;
    const __nv_bfloat16* vbh = vhg + (size_t)b * T_ * KVD_ + g * HD_;
    const __nv_bfloat16* vbl = vlg + (size_t)b * T_ * KVD_ + g * HD_;

    for (int kt = 0; kt < T_ / 64; kt++) {
        // ---- load K/V tiles (64x64 bf16 hi/lo), pure float4 copies ----
#pragma unroll
        for (int t = 0; t < 2; t++) {
            int idx = tid + t * 256;       // 0..511 float4 (64 rows x 8 slots)
            int r = idx >> 3, sl = (idx & 7) << 3;
            size_t go = (size_t)(kt*64 + r) * KVD_ + sl;
            *(float4*)&kh[r*AT_SA + sl] = *(const float4*)(kbh + go);
            *(float4*)&kl[r*AT_SA + sl] = *(const float4*)(kbl + go);
            *(float4*)&vh[r*AT_SA + sl] = *(const float4*)(vbh + go);
            *(float4*)&vl[r*AT_SA + sl] = *(const float4*)(vbl + go);
        }
        __syncthreads();

        // ---- scores S = Q K^T (3-pass split) ----
        float s[8][4];
#pragma unroll
        for (int nf = 0; nf < 8; nf++)
#pragma unroll
            for (int t = 0; t < 4; t++) s[nf][t] = 0.f;
#pragma unroll
        for (int kf = 0; kf < 4; kf++) {
            unsigned int afh[4], afl[4];
            ldm_x4(afh, aQH + (unsigned int)(kf * 32));
            ldm_x4(afl, aQL + (unsigned int)(kf * 32));
#pragma unroll
            for (int nf = 0; nf < 8; nf++) {
                unsigned int bfh[2], bfl[2];
                ldm_x2(bfh, bKH + (unsigned int)((nf*8*AT_SA + kf*16) * 2));
                ldm_x2(bfl, bKL + (unsigned int)((nf*8*AT_SA + kf*16) * 2));
                mma_bf16(s[nf], afh, bfh);
                mma_bf16(s[nf], afh, bfl);
                mma_bf16(s[nf], afl, bfh);
            }
        }

        // ---- relpos bias from qe table ----
        const int qg0 = q0 + r0l;
#pragma unroll
        for (int nf = 0; nf < 8; nf++) {
            int kgb = kt*64 + nf*8 + ((lane & 3) << 1);
#pragma unroll
            for (int t = 0; t < 4; t++) {
                int row = r0l + ((t >> 1) << 3);
                int qg  = qg0 + ((t >> 1) << 3);
                int kg  = kgb + (t & 1);
                int dlt = qg - kg;
                dlt = max(-127, min(127, dlt)) + 127;
                s[nf][t] += __bfloat162float(qem[row*256 + dlt]);
            }
        }

        // ---- online softmax ----
        float tm0 = -1e30f, tm1 = -1e30f;
#pragma unroll
        for (int nf = 0; nf < 8; nf++) {
            tm0 = fmaxf(tm0, fmaxf(s[nf][0], s[nf][1]));
            tm1 = fmaxf(tm1, fmaxf(s[nf][2], s[nf][3]));
        }
        tm0 = fmaxf(tm0, __shfl_xor_sync(0xffffffffu, tm0, 1));
        tm0 = fmaxf(tm0, __shfl_xor_sync(0xffffffffu, tm0, 2));
        tm1 = fmaxf(tm1, __shfl_xor_sync(0xffffffffu, tm1, 1));
        tm1 = fmaxf(tm1, __shfl_xor_sync(0xffffffffu, tm1, 2));
        float mn0 = fmaxf(m0, tm0), mn1 = fmaxf(m1, tm1);
        float sc0 = __expf(m0 - mn0), sc1 = __expf(m1 - mn1);
        float ls0 = 0.f, ls1 = 0.f;
#pragma unroll
        for (int nf = 0; nf < 8; nf++) {
            s[nf][0] = __expf(s[nf][0] - mn0);
            s[nf][1] = __expf(s[nf][1] - mn0);
            s[nf][2] = __expf(s[nf][2] - mn1);
            s[nf][3] = __expf(s[nf][3] - mn1);
            ls0 += s[nf][0] + s[nf][1];
            ls1 += s[nf][2] + s[nf][3];
        }
        ls0 += __shfl_xor_sync(0xffffffffu, ls0, 1);
        ls0 += __shfl_xor_sync(0xffffffffu, ls0, 2);
        ls1 += __shfl_xor_sync(0xffffffffu, ls1, 1);
        ls1 += __shfl_xor_sync(0xffffffffu, ls1, 2);
        l0 = l0 * sc0 + ls0;  m0 = mn0;
        l1 = l1 * sc1 + ls1;  m1 = mn1;
#pragma unroll
        for (int nf = 0; nf < 8; nf++) {
            acc_o[nf][0] *= sc0; acc_o[nf][1] *= sc0;
            acc_o[nf][2] *= sc1; acc_o[nf][3] *= sc1;
        }

        // ---- store P split into warp-private stripe ----
        {
            int cc = ((lane & 3) << 1);
#pragma unroll
            for (int nf = 0; nf < 8; nf++) {
                int c0i = cc + nf*8;
                *(unsigned int*)&ph[r0l*AT_SA + c0i]     = pack_hi2(s[nf][0], s[nf][1]);
                *(unsigned int*)&pl[r0l*AT_SA + c0i]     = pack_lo2(s[nf][0], s[nf][1]);
                *(unsigned int*)&ph[(r0l+8)*AT_SA + c0i] = pack_hi2(s[nf][2], s[nf][3]);
                *(unsigned int*)&pl[(r0l+8)*AT_SA + c0i] = pack_lo2(s[nf][2], s[nf][3]);
            }
        }
        __syncwarp();

        // ---- acc_o += P V (3-pass split; V via ldmatrix.trans) ----
#pragma unroll
        for (int kf = 0; kf < 4; kf++) {
            unsigned int aph[4], apl[4];
            ldm_x4(aph, aPH + (unsigned int)(kf * 32));
            ldm_x4(apl, aPL + (unsigned int)(kf * 32));
#pragma unroll
            for (int nf = 0; nf < 8; nf++) {
                unsigned int bvh[2], bvl[2];
                ldm_x2_trans(bvh, bVH + (unsigned int)((kf*16*AT_SA + nf*8) * 2));
                ldm_x2_trans(bvl, bVL + (unsigned int)((kf*16*AT_SA + nf*8) * 2));
                mma_bf16(acc_o[nf], aph, bvh);
                mma_bf16(acc_o[nf], aph, bvl);
                mma_bf16(acc_o[nf], apl, bvh);
            }
        }
        __syncthreads();
    }

    // ---- epilogue: write split bf16 output directly ----
    float inv0 = 1.f / l0, inv1 = 1.f / l1;
    size_t ob = ((size_t)(b * T_ + q0 + r0l)) * D_ + h * HD_;
#pragma unroll
    for (int nf = 0; nf < 8; nf++) {
        int cc = nf*8 + ((lane & 3) << 1);
        float a0 = acc_o[nf][0] * inv0, a1 = acc_o[nf][1] * inv0;
        float a2 = acc_o[nf][2] * inv1, a3 = acc_o[nf][3] * inv1;
        *(unsigned int*)&ohg[ob + cc]               = pack_hi2(a0, a1);
        *(unsigned int*)&olg[ob + cc]               = pack_lo2(a0, a1);
        *(unsigned int*)&ohg[ob + (size_t)8*D_ + cc] = pack_hi2(a2, a3);
        *(unsigned int*)&olg[ob + (size_t)8*D_ + cc] = pack_lo2(a2, a3);
    }
}

// ============================================================
extern "C" void kernel_launch(void* const* d_in, const int* in_sizes, int n_in,
                              void* d_out, int out_size)
{
    const float* x  = (const float*)d_in[0];
    const float* Wq = (const float*)d_in[1];
    const float* Wk = (const float*)d_in[2];
    const float* Wv = (const float*)d_in[3];
    const float* Wo = (const float*)d_in[4];
    const float* E  = (const float*)d_in[5];
    float* out = (float*)d_out;

    __nv_bfloat16* xh = 0;  __nv_bfloat16* xl = 0;
    __nv_bfloat16* qh = 0;  __nv_bfloat16* ql = 0;
    __nv_bfloat16* kh = 0;  __nv_bfloat16* kl = 0;
    __nv_bfloat16* vh = 0;  __nv_bfloat16* vl = 0;
    __nv_bfloat16* oh = 0;  __nv_bfloat16* ol = 0;
    __nv_bfloat16* wqh = 0; __nv_bfloat16* wql = 0;
    __nv_bfloat16* wkh = 0; __nv_bfloat16* wkl = 0;
    __nv_bfloat16* wvh = 0; __nv_bfloat16* wvl = 0;
    __nv_bfloat16* woh = 0; __nv_bfloat16* wol = 0;
    cudaGetSymbolAddress((void**)&xh, g_xh);
    cudaGetSymbolAddress((void**)&xl, g_xl);
    cudaGetSymbolAddress((void**)&qh, g_qh);
    cudaGetSymbolAddress((void**)&ql, g_ql);
    cudaGetSymbolAddress((void**)&kh, g_kh);
    cudaGetSymbolAddress((void**)&kl, g_kl);
    cudaGetSymbolAddress((void**)&vh, g_vh);
    cudaGetSymbolAddress((void**)&vl, g_vl);
    cudaGetSymbolAddress((void**)&oh, g_oh);
    cudaGetSymbolAddress((void**)&ol, g_ol);
    cudaGetSymbolAddress((void**)&wqh, g_wqh);
    cudaGetSymbolAddress((void**)&wql, g_wql);
    cudaGetSymbolAddress((void**)&wkh, g_wkh);
    cudaGetSymbolAddress((void**)&wkl, g_wkl);
    cudaGetSymbolAddress((void**)&wvh, g_wvh);
    cudaGetSymbolAddress((void**)&wvl, g_wvl);
    cudaGetSymbolAddress((void**)&woh, g_woh);
    cudaGetSymbolAddress((void**)&wol, g_wol);

    cudaFuncSetAttribute(attn_kernel, cudaFuncAttributeMaxDynamicSharedMemorySize,
                         ATTN_SMEM_BYTES);
    cudaFuncSetAttribute(gemm_tc, cudaFuncAttributeMaxDynamicSharedMemorySize,
                         GEMM_SMEM_BYTES);
    cudaFuncSetAttribute(gemm_tc_split, cudaFuncAttributeMaxDynamicSharedMemorySize,
                         GEMM_SMEM_BYTES);

    const int M = 8192;                  // B_*T_
    const float qscale = 0.125f;         // 1/sqrt(64)

    int nx4 = (M * D_) / 4;
    int nw4 = (D_ * D_) / 4;
    int nk4 = (KVD_ * D_) / 4;

    split_bf16<<<(nx4 + 255) / 256, 256>>>(x, xh, xl, nx4);
    split_bf16<<<(nw4 + 255) / 256, 256>>>(Wq, wqh, wql, nw4);
    split_bf16<<<(nk4 + 255) / 256, 256>>>(Wk, wkh, wkl, nk4);
    split_bf16<<<(nk4 + 255) / 256, 256>>>(Wv, wvh, wvl, nk4);
    split_bf16<<<(nw4 + 255) / 256, 256>>>(Wo, woh, wol, nw4);

    dim3 gq(8, 64);    // D_/128, M/128
    dim3 gkv(2, 64);   // KVD_/128, M/128
    gemm_tc_split<<<gq,  256, GEMM_SMEM_BYTES>>>(xh, xl, wqh, wql, qh, ql, M, D_, D_, qscale);
    gemm_tc_split<<<gkv, 256, GEMM_SMEM_BYTES>>>(xh, xl, wkh, wkl, kh, kl, M, KVD_, D_, 1.0f);
    gemm_tc_split<<<gkv, 256, GEMM_SMEM_BYTES>>>(xh, xl, wvh, wvl, vh, vl, M, KVD_, D_, 1.0f);

    dim3 ga(8, 16, 8);  // T_/128, H_, B_
    attn_kernel<<<ga, 256, ATTN_SMEM_BYTES>>>(qh, ql, kh, kl, vh, vl, E, oh, ol);

    gemm_tc<<<gq, 256, GEMM_SMEM_BYTES>>>(oh, ol, woh, wol, out, M, D_, D_, 1.0f);
}